// round 6
// baseline (speedup 1.0000x reference)
#include <cuda_runtime.h>
#include <math.h>

// Problem constants
#define BATCH    4
#define HW_IN    (512 * 512)         // gaussians per batch (2^18)
#define W_OUT    1024
#define HW_OUT   (1024 * 1024)
#define N_GAUSS  (BATCH * HW_IN)     // 1,048,576
#define OUT_ELEMS (BATCH * 3 * HW_OUT)

// Border privatization: ~73% of gaussians clamp onto the 1-pixel border ring.
// Channel-interleaved replicated accumulator: one red.v4 per border gaussian.
#define R_REP    16
#define BI_N     4096                          // compact border slots per batch
// g_border layout: [rep][b][bi] -> float4 (r,g,b,unused)
__device__ float4 g_border[R_REP * BATCH * BI_N];          // 4 MB
// g_bsum layout:   [b][bi] -> float4 (replica-reduced)
__device__ float4 g_bsum[BATCH * BI_N];                    // 256 KB

#define N4_OUT      (OUT_ELEMS / 4)            // 3,145,728
#define N4_SCRATCH  (R_REP * BATCH * BI_N)     //   262,144
#define N4_TOTAL    (N4_OUT + N4_SCRATCH)      // 3,407,872
#define N4_HALF     (N4_TOTAL / 2)             // 1,703,936

// ---------------------------------------------------------------------------
// Kernel 1: zero framebuffer + border scratch. 2 float4 per thread for MLP.
// ---------------------------------------------------------------------------
__global__ void gr_zero_kernel(float4* __restrict__ out) {
    int i = blockIdx.x * blockDim.x + threadIdx.x;
    float4 z = make_float4(0.f, 0.f, 0.f, 0.f);
    #pragma unroll
    for (int h = 0; h < 2; ++h) {
        int j = i + h * N4_HALF;
        if (j < N4_OUT)           out[j] = z;
        else if (j < N4_TOTAL)    g_border[j - N4_OUT] = z;
    }
}

// ---------------------------------------------------------------------------
// Kernel 2: scatter. Interior -> direct scalar atomics (spread, cheap).
// Border -> one red.global.add.v4.f32 into replicated interleaved scratch,
// replica indexed by LANE so same-warp corner hits never share an address.
// ---------------------------------------------------------------------------
__global__ void gr_scatter_kernel(const float* __restrict__ uv,
                                  const float* __restrict__ pos,
                                  float* __restrict__ out) {
    int gid = blockIdx.x * blockDim.x + threadIdx.x;
    if (gid >= N_GAUSS) return;
    int b = gid >> 18;            // / HW_IN
    int n = gid & (HW_IN - 1);

    const float* uvb  = uv  + (size_t)b * 14 * HW_IN;
    const float* posb = pos + (size_t)b * 3 * HW_IN;

    // batch the 8 loads for MLP
    float p0 = posb[n];
    float p1 = posb[HW_IN + n];
    float u0 = uvb[n];
    float u1 = uvb[HW_IN + n];
    float uo = uvb[10 * HW_IN + n];
    float c0 = uvb[11 * HW_IN + n];
    float c1 = uvb[12 * HW_IN + n];
    float c2 = uvb[13 * HW_IN + n];

    float x = p0 + u0;
    float y = p1 + u1;
    float o = 1.0f / (1.0f + __expf(-uo));
    float r  = c0 * o;
    float g  = c1 * o;
    float bl = c2 * o;

    // truncating cast then clamp (matches .astype(int32) + clip)
    int px = (int)((x + 1.0f) * 0.5f * (float)W_OUT);
    int py = (int)((y + 1.0f) * 0.5f * (float)W_OUT);
    px = min(max(px, 0), W_OUT - 1);
    py = min(max(py, 0), W_OUT - 1);

    bool border = (px == 0) | (px == W_OUT - 1) | (py == 0) | (py == W_OUT - 1);
    if (border) {
        // compact border index:
        //   py==0    -> px            [0,1024)
        //   py==1023 -> 1024+px       [1024,2048)
        //   px==0    -> 2048+py       (py in 1..1022)
        //   px==1023 -> 3072+py
        int bi = (py == 0)         ? px
               : (py == W_OUT - 1) ? (1024 + px)
               : (px == 0)         ? (2048 + py)
                                   : (3072 + py);
        int rep = gid & (R_REP - 1);    // lane-indexed: spreads same-warp corners
        float* p = (float*)&g_border[(rep * BATCH + b) * BI_N + bi];
        asm volatile("red.global.add.v4.f32 [%0], {%1, %2, %3, %4};"
                     :: "l"(p), "f"(r), "f"(g), "f"(bl), "f"(0.0f)
                     : "memory");
    } else {
        int idx = py * W_OUT + px;
        float* ob = out + (size_t)b * 3 * HW_OUT;
        atomicAdd(ob + idx,              r);
        atomicAdd(ob + HW_OUT + idx,     g);
        atomicAdd(ob + 2 * HW_OUT + idx, bl);
    }
}

// ---------------------------------------------------------------------------
// Kernel 3: collapse the R_REP replicas -> g_bsum. 16384 threads, one slot each.
// ---------------------------------------------------------------------------
__global__ void gr_repreduce_kernel() {
    int t = blockIdx.x * blockDim.x + threadIdx.x;   // [0, BATCH*BI_N)
    if (t >= BATCH * BI_N) return;
    float a0 = 0.f, a1 = 0.f, a2 = 0.f;
    #pragma unroll
    for (int rp = 0; rp < R_REP; ++rp) {
        float4 v = g_border[rp * BATCH * BI_N + t];
        a0 += v.x; a1 += v.y; a2 += v.z;
    }
    g_bsum[t] = make_float4(a0, a1, a2, 0.f);
}

// ---------------------------------------------------------------------------
// Kernel 4: fused border-add + clamp. 2 float4 per thread (buffer halves) for
// doubled bytes-in-flight. Border pixels receive contributions ONLY via the
// privatized path, so plain add is race-free.
// ---------------------------------------------------------------------------
__global__ void gr_final_kernel(float4* __restrict__ out) {
    int i0 = blockIdx.x * blockDim.x + threadIdx.x;
    if (i0 >= N4_OUT / 2) return;

    #pragma unroll
    for (int h = 0; h < 2; ++h) {
        int i = i0 + h * (N4_OUT / 2);

        int pc   = i >> 18;          // b*3 + c  (262144 float4 per plane)
        int e    = i & 0x3FFFF;
        int row  = e >> 8;           // 256 float4 per row
        int col4 = e & 255;
        int b = pc / 3;
        int c = pc - 3 * b;

        float4 v = out[i];
        const float* gb = (const float*)(g_bsum + b * BI_N);   // [bi][4]

        if (row == 0) {
            int px0 = col4 << 2;
            v.x += gb[(px0 + 0) * 4 + c];
            v.y += gb[(px0 + 1) * 4 + c];
            v.z += gb[(px0 + 2) * 4 + c];
            v.w += gb[(px0 + 3) * 4 + c];
        } else if (row == W_OUT - 1) {
            int bi0 = 1024 + (col4 << 2);
            v.x += gb[(bi0 + 0) * 4 + c];
            v.y += gb[(bi0 + 1) * 4 + c];
            v.z += gb[(bi0 + 2) * 4 + c];
            v.w += gb[(bi0 + 3) * 4 + c];
        } else if (col4 == 0) {
            v.x += gb[(2048 + row) * 4 + c];
        } else if (col4 == 255) {
            v.w += gb[(3072 + row) * 4 + c];
        }

        v.x = __saturatef(v.x);
        v.y = __saturatef(v.y);
        v.z = __saturatef(v.z);
        v.w = __saturatef(v.w);
        out[i] = v;
    }
}

// ---------------------------------------------------------------------------
extern "C" void kernel_launch(void* const* d_in, const int* in_sizes, int n_in,
                              void* d_out, int out_size) {
    const float* uv  = (const float*)d_in[0];   // [4,14,512,512]
    const float* pos = (const float*)d_in[1];   // [4,3,512,512]
    float* out = (float*)d_out;                 // [4,3,1024,1024]

    const int TPB = 256;

    gr_zero_kernel<<<(N4_HALF + TPB - 1) / TPB, TPB>>>((float4*)out);
    gr_scatter_kernel<<<(N_GAUSS + TPB - 1) / TPB, TPB>>>(uv, pos, out);
    gr_repreduce_kernel<<<(BATCH * BI_N + TPB - 1) / TPB, TPB>>>();
    gr_final_kernel<<<(N4_OUT / 2 + TPB - 1) / TPB, TPB>>>((float4*)out);
}